// round 12
// baseline (speedup 1.0000x reference)
#include <cuda_runtime.h>
#include <cuda_fp16.h>
#include <cstdint>
#include <math.h>

#define NV 4096
#define HD 64
#define RV 3
#define WPR 128   // 32-bit words per adjacency row
#define NSPL 4    // j-splits of 1024

// ---------------- scratch ------------------------------------------------------
__device__ uint32_t g_bits[RV * NV * WPR];        // packed adjacency (6.3 MB)
__device__ float g_fi[RV * NV];
__device__ float g_fj[RV * NV];
__device__ __half g_Whh[RV * NV * HD];            // Wh in f16, [r][j][c]
__device__ __half g_num[RV * NSPL * NV * HD];     // per (r, j-split) numerators (f16)
__device__ float g_den[RV * NSPL * NV];

__device__ __forceinline__ void cpa16(uint32_t d, const void* s) {
    asm volatile("cp.async.cg.shared.global [%0], [%1], 16;" :: "r"(d), "l"(s));
}
__device__ __forceinline__ void mma16816(float* d, const uint32_t* a,
                                         uint32_t b0, uint32_t b1) {
    asm volatile(
        "mma.sync.aligned.m16n8k16.row.col.f32.f16.f16.f32 "
        "{%0,%1,%2,%3}, {%4,%5,%6,%7}, {%8,%9}, {%0,%1,%2,%3};"
        : "+f"(d[0]), "+f"(d[1]), "+f"(d[2]), "+f"(d[3])
        : "r"(a[0]), "r"(a[1]), "r"(a[2]), "r"(a[3]), "r"(b0), "r"(b1));
}

// ---------------- gemm compute + epilogue (64-row tile) -------------------------
// Hs must hold H tile as [k][i]; Wss gets W tile [k][c]. Emits Whh(f16) + fi/fj.
template <int K>
__device__ __forceinline__ void gemm_compute_epilogue(
    float (*Hs)[64], float (*Wss)[64], int r, int rowbase,
    const float* __restrict__ avec) {
    int tid = threadIdx.x;
    int tx = tid & 15, ty = tid >> 4;
    int i0 = ty * 4, c0 = tx * 4;
    float acc[4][4] = {};

#pragma unroll 8
    for (int kk = 0; kk < 64; kk++) {
        float4 a = *(const float4*)&Hs[kk][i0];
        float4 b = *(const float4*)&Wss[kk][c0];
        float av[4] = {a.x, a.y, a.z, a.w};
        float bv[4] = {b.x, b.y, b.z, b.w};
#pragma unroll
        for (int ii = 0; ii < 4; ii++)
#pragma unroll
            for (int jj = 0; jj < 4; jj++)
                acc[ii][jj] = fmaf(av[ii], bv[jj], acc[ii][jj]);
    }
    __syncthreads();

#pragma unroll
    for (int ii = 0; ii < 4; ii++)
        *(float4*)&Hs[i0 + ii][c0] =
            make_float4(acc[ii][0], acc[ii][1], acc[ii][2], acc[ii][3]);
    __syncthreads();

    // f16 Wh store: [j][c]
    {
        int i = tid >> 2, cb = (tid & 3) * 16;
        uint32_t h2v[8];
#pragma unroll
        for (int q = 0; q < 8; q++) {
            __half2 h = __floats2half2_rn(Hs[i][cb + 2 * q], Hs[i][cb + 2 * q + 1]);
            h2v[q] = *reinterpret_cast<uint32_t*>(&h);
        }
        uint32_t* dst =
            (uint32_t*)(g_Whh + ((size_t)(r * NV + rowbase + i)) * HD + cb);
        *(uint4*)dst = make_uint4(h2v[0], h2v[1], h2v[2], h2v[3]);
        *(uint4*)(dst + 4) = make_uint4(h2v[4], h2v[5], h2v[6], h2v[7]);
    }

    int warp = tid >> 5, lane = tid & 31;
    const float* ar = avec + r * 2 * HD;
#pragma unroll
    for (int s = 0; s < 8; s++) {
        int i = warp * 8 + s;
        float h1 = Hs[i][lane], h2 = Hs[i][lane + 32];
        float pl = h1 * ar[lane] + h2 * ar[lane + 32];
        float pr = h1 * ar[HD + lane] + h2 * ar[HD + lane + 32];
#pragma unroll
        for (int o = 16; o; o >>= 1) {
            pl += __shfl_down_sync(0xFFFFFFFFu, pl, o);
            pr += __shfl_down_sync(0xFFFFFFFFu, pr, o);
        }
        if (lane == 0) {
            g_fi[r * NV + rowbase + i] = pl;
            g_fj[r * NV + rowbase + i] = pr;
        }
    }
}

// ---------------- 1. fused: pack (blocks >=192) + layer-1 gemm (blocks <192) ----
__global__ void __launch_bounds__(256) fused_pack_gemm1(
    const float* __restrict__ Z, const int* __restrict__ A0,
    const int* __restrict__ A1, const int* __restrict__ A2,
    const float* __restrict__ W1, const float* __restrict__ a1) {
    __shared__ float Hs[64][64];
    __shared__ float Wss[64][64];
    int bx = blockIdx.x;
    int tid = threadIdx.x;
    if (bx < 192) {
        int r = bx >> 6, rowbase = (bx & 63) * 64;
        const float* Wr = W1 + (size_t)r * 128 * HD;
        float acc[4][4] = {};
        int tx = tid & 15, ty = tid >> 4;
        int i0 = ty * 4, c0 = tx * 4;
        for (int kt = 0; kt < 128; kt += 64) {
            {
                int i = tid >> 2, kk0 = (tid & 3) << 4;
                const float* src = Z + (size_t)(rowbase + i) * 128 + kt + kk0;
#pragma unroll
                for (int q = 0; q < 4; q++) {
                    float4 v = *(const float4*)(src + 4 * q);
                    Hs[kk0 + 4 * q + 0][i] = v.x;
                    Hs[kk0 + 4 * q + 1][i] = v.y;
                    Hs[kk0 + 4 * q + 2][i] = v.z;
                    Hs[kk0 + 4 * q + 3][i] = v.w;
                }
                const float4* wsrc = (const float4*)(Wr + (size_t)kt * HD);
                float4* wdst = (float4*)&Wss[0][0];
#pragma unroll
                for (int q = 0; q < 4; q++)
                    wdst[tid + 256 * q] = wsrc[tid + 256 * q];
            }
            __syncthreads();
#pragma unroll 8
            for (int kk = 0; kk < 64; kk++) {
                float4 a = *(const float4*)&Hs[kk][i0];
                float4 b = *(const float4*)&Wss[kk][c0];
                float av[4] = {a.x, a.y, a.z, a.w};
                float bv[4] = {b.x, b.y, b.z, b.w};
#pragma unroll
                for (int ii = 0; ii < 4; ii++)
#pragma unroll
                    for (int jj = 0; jj < 4; jj++)
                        acc[ii][jj] = fmaf(av[ii], bv[jj], acc[ii][jj]);
            }
            __syncthreads();
        }
        // write partial sums into Hs as the "computed" tile, then shared epilogue
#pragma unroll
        for (int ii = 0; ii < 4; ii++)
            *(float4*)&Hs[i0 + ii][c0] =
                make_float4(acc[ii][0], acc[ii][1], acc[ii][2], acc[ii][3]);
        __syncthreads();
        {
            int i = tid >> 2, cb = (tid & 3) * 16;
            uint32_t h2v[8];
#pragma unroll
            for (int q = 0; q < 8; q++) {
                __half2 h =
                    __floats2half2_rn(Hs[i][cb + 2 * q], Hs[i][cb + 2 * q + 1]);
                h2v[q] = *reinterpret_cast<uint32_t*>(&h);
            }
            uint32_t* dst =
                (uint32_t*)(g_Whh + ((size_t)(r * NV + rowbase + i)) * HD + cb);
            *(uint4*)dst = make_uint4(h2v[0], h2v[1], h2v[2], h2v[3]);
            *(uint4*)(dst + 4) = make_uint4(h2v[4], h2v[5], h2v[6], h2v[7]);
        }
        int warp = tid >> 5, lane = tid & 31;
        const float* ar = a1 + r * 2 * HD;
#pragma unroll
        for (int s = 0; s < 8; s++) {
            int i = warp * 8 + s;
            float h1 = Hs[i][lane], h2 = Hs[i][lane + 32];
            float pl = h1 * ar[lane] + h2 * ar[lane + 32];
            float pr = h1 * ar[HD + lane] + h2 * ar[HD + lane + 32];
#pragma unroll
            for (int o = 16; o; o >>= 1) {
                pl += __shfl_down_sync(0xFFFFFFFFu, pl, o);
                pr += __shfl_down_sync(0xFFFFFFFFu, pr, o);
            }
            if (lane == 0) {
                g_fi[r * NV + rowbase + i] = pl;
                g_fj[r * NV + rowbase + i] = pr;
            }
        }
        return;
    }
    // pack path
    const int TOTQ = RV * NV * NV / 4;
    const int stride = 4096 * 256;
    int lane = threadIdx.x & 31;
    for (int t = (bx - 192) * 256 + threadIdx.x; t < TOTQ; t += stride) {
        int r = t >> 22;
        const int4* A = (const int4*)((r == 0) ? A0 : (r == 1) ? A1 : A2);
        int4 v = A[t & 0x3FFFFF];
        uint32_t nib = (v.x != 0 ? 1u : 0u) | (v.y != 0 ? 2u : 0u) |
                       (v.z != 0 ? 4u : 0u) | (v.w != 0 ? 8u : 0u);
        uint32_t m = nib << ((lane & 7) * 4);
        m |= __shfl_xor_sync(0xFFFFFFFFu, m, 1);
        m |= __shfl_xor_sync(0xFFFFFFFFu, m, 2);
        m |= __shfl_xor_sync(0xFFFFFFFFu, m, 4);
        if ((lane & 7) == 0) g_bits[t >> 3] = m;
    }
}

// ---------------- 2. fused combine(layer1) + layer-2 gemm -----------------------
// grid (64, 3): block (rowbase, r). Reconstructs H1 rows from g_num/g_den
// directly into the smem tile (transposed [k][i]), then runs the K=64 gemm.
__global__ void __launch_bounds__(256) combine_gemm2_kernel(
    const float* __restrict__ Wmat, const float* __restrict__ avec,
    const float* __restrict__ bvec) {
    __shared__ float Hs[64][64];                  // [k=c1][i]
    __shared__ float Wss[64][64];
    int tid = threadIdx.x;
    int r = blockIdx.y;
    int rowbase = blockIdx.x * 64;

    // W load first (long-latency global, overlaps combine loads)
    {
        const float4* wsrc = (const float4*)(Wmat + (size_t)r * 64 * HD);
        float4* wdst = (float4*)&Wss[0][0];
#pragma unroll
        for (int q = 0; q < 4; q++) wdst[tid + 256 * q] = wsrc[tid + 256 * q];
    }

    // combine: H1[i][c] = relu(b[c] + sum_r2 num/den), written transposed
    {
        int row = tid >> 2, cg = tid & 3;
        int i = rowbase + row;
        float dinv[RV];
#pragma unroll
        for (int r2 = 0; r2 < RV; r2++) {
            float d = 0.f;
#pragma unroll
            for (int s = 0; s < NSPL; s++)
                d += g_den[(size_t)(r2 * NSPL + s) * NV + i];
            dinv[r2] = (d != 0.f) ? __frcp_rn(d) : 0.f;
        }
#pragma unroll
        for (int cc = 0; cc < 16; cc += 2) {
            int c = cg * 16 + cc;
            float2 v = make_float2(bvec[c], bvec[c + 1]);
#pragma unroll
            for (int r2 = 0; r2 < RV; r2++) {
                float2 num = make_float2(0.f, 0.f);
#pragma unroll
                for (int s = 0; s < NSPL; s++) {
                    uint32_t nv = *(const uint32_t*)&g_num[
                        (((size_t)(r2 * NSPL + s) * NV) + i) * HD + c];
                    float2 a = __half22float2(*(__half2*)&nv);
                    num.x += a.x; num.y += a.y;
                }
                v.x += num.x * dinv[r2];
                v.y += num.y * dinv[r2];
            }
            Hs[c][i - rowbase] = fmaxf(v.x, 0.f);
            Hs[c + 1][i - rowbase] = fmaxf(v.y, 0.f);
        }
    }
    __syncthreads();

    gemm_compute_epilogue<64>(Hs, Wss, r, rowbase, avec);
}

// ---------------- 3. fused alpha-gen + HMMA aggregation -------------------------
// grid (32 i-tiles of 128 rows, 3 r, 4 j-splits of 1024); 128 threads / 4 warps.
__global__ void __launch_bounds__(128, 4) attn_hmma_kernel() {
    int tid = threadIdx.x;
    int itile = blockIdx.x, r = blockIdx.y, split = blockIdx.z;
    int rowbase = itile * 128;
    int jw0 = split * 1024;

    __shared__ __align__(1024) uint8_t sB[3][8192];  // 64j x 64c f16, swizzled
    __shared__ uint32_t sBits[128 * 36];             // 128 rows, stride 36 words
    __shared__ uint4 sEF[256];                       // (group, tg) -> {E2lo,E2hi,F2lo,F2hi}
    __shared__ uint2 sLut[16];                       // nibble -> 2 half2 masks

    uint32_t sBu[3] = {(uint32_t)__cvta_generic_to_shared(&sB[0][0]),
                       (uint32_t)__cvta_generic_to_shared(&sB[1][0]),
                       (uint32_t)__cvta_generic_to_shared(&sB[2][0])};
    uint32_t sBitsu = (uint32_t)__cvta_generic_to_shared(sBits);

    if (tid < 16)
        sLut[tid] = make_uint2(
            ((tid & 1) ? 0xFFFFu : 0u) | ((tid & 2) ? 0xFFFF0000u : 0u),
            ((tid & 4) ? 0xFFFFu : 0u) | ((tid & 8) ? 0xFFFF0000u : 0u));

    // stage adjacency bits for this tile: 128 rows x 128B (once, coalesced)
#pragma unroll
    for (int q = 0; q < 8; q++) {
        int idx = tid + 128 * q;
        int row = idx >> 3, w16 = idx & 7;
        const uint32_t* src = g_bits + (size_t)(r * NV + rowbase + row) * WPR +
                              split * 32 + w16 * 4;
        cpa16(sBitsu + (row * 36 + w16 * 4) * 4, src);
    }

    // B chunk stager: rows placed at sigma(j) to match lane-contiguous j perm
    auto stage = [&](int ch, int buf) {
#pragma unroll
        for (int q = 0; q < 4; q++) {
            int g = tid + 128 * q;
            int j64 = g >> 3, c8 = g & 7;
            int j16 = j64 & 15, t = j16 >> 2, q2 = j16 & 3;
            int srow = (j64 & ~15) + 2 * t + (q2 & 1) + ((q2 >> 1) << 3);
            const __half* src =
                g_Whh + ((size_t)(r * NV + jw0 + ch * 64 + j64)) * HD + c8 * 8;
            cpa16(sBu[buf] + srow * 128 + 16 * (c8 ^ (srow & 7)), src);
        }
        asm volatile("cp.async.commit_group;" ::: "memory");
    };
    stage(0, 0);        // G0: bits + B0
    stage(1, 1);        // G1: B1

    // compute EF window (Ej = exp(fj), Fj = exp(0.2 fj)); entry e covers
    // j = jw0 + 4e + {0,1,2,3}, matching the sigma(j) B permutation.
    {
        const float* fjp = g_fj + r * NV + jw0;
#pragma unroll
        for (int q = 0; q < 2; q++) {
            int e = tid + 128 * q;
            float4 f = *(const float4*)&fjp[e * 4];
            __half2 e01 = __floats2half2_rn(__expf(f.x), __expf(f.y));
            __half2 e23 = __floats2half2_rn(__expf(f.z), __expf(f.w));
            __half2 f01 =
                __floats2half2_rn(__expf(0.2f * f.x), __expf(0.2f * f.y));
            __half2 f23 =
                __floats2half2_rn(__expf(0.2f * f.z), __expf(0.2f * f.w));
            sEF[e] = make_uint4(*reinterpret_cast<uint32_t*>(&e01),
                                *reinterpret_cast<uint32_t*>(&e23),
                                *reinterpret_cast<uint32_t*>(&f01),
                                *reinterpret_cast<uint32_t*>(&f23));
        }
    }

    int l = tid & 31, w = tid >> 5;
    int g4 = l >> 2, tg = l & 3;
    int rowloc = w * 32 + g4;                     // rows rowloc + 8*rr, rr<4
    int rowg = rowbase + rowloc;
    __half2 Ei2[4], Fi2[4];
#pragma unroll
    for (int rr = 0; rr < 4; rr++) {
        float u = g_fi[r * NV + rowg + 8 * rr];
        float ei = __expf(fminf(0.8f * u, 0.f));   // exp(u - lrelu(u))
        float fi_ = __expf(fminf(-0.8f * u, 0.f)); // exp(0.2u - lrelu(u))
        Ei2[rr] = __floats2half2_rn(ei, ei);
        Fi2[rr] = __floats2half2_rn(fi_, fi_);
    }

    int row_l = ((l >> 3) & 1) * 8 + (l & 7);     // ldmatrix row within k16
    int x_l = (l >> 4) ^ (row_l & 7);             // swizzle term

    float acc[2][8][4] = {};                      // [m-tile][n8][frag]
    float accD[2][4] = {};
    uint32_t bone = (l < 4) ? 0x3C003C00u : 0u;   // ones column (den)

    for (int ch = 0; ch < 16; ch++) {
        int buf = ch % 3;
        if (ch < 15)
            asm volatile("cp.async.wait_group 1;" ::: "memory");
        else
            asm volatile("cp.async.wait_group 0;" ::: "memory");
        __syncthreads();
        if (ch + 2 < 16) stage(ch + 2, (ch + 2) % 3);
        uint2 wbv[4];
#pragma unroll
        for (int rr = 0; rr < 4; rr++)
            wbv[rr] = *(const uint2*)&sBits[(rowloc + 8 * rr) * 36 + ch * 2];
#pragma unroll
        for (int ks = 0; ks < 4; ks++) {
            uint4 EF = sEF[ch * 16 + ks * 4 + tg];
            __half2 E2lo = *(__half2*)&EF.x, E2hi = *(__half2*)&EF.y;
            __half2 F2lo = *(__half2*)&EF.z, F2hi = *(__half2*)&EF.w;
            uint32_t afr[2][4];
#pragma unroll
            for (int rr = 0; rr < 4; rr++) {
                uint32_t wword = (ks < 2) ? wbv[rr].x : wbv[rr].y;
                uint32_t nib = (wword >> ((ks & 1) * 16 + tg * 4)) & 0xFu;
                uint2 mk = sLut[nib];
                __half2 plo =
                    __hmax2(__hmul2(Ei2[rr], E2lo), __hmul2(Fi2[rr], F2lo));
                __half2 phi =
                    __hmax2(__hmul2(Ei2[rr], E2hi), __hmul2(Fi2[rr], F2hi));
                int mt = rr >> 1, hi = rr & 1;
                afr[mt][hi] = (*reinterpret_cast<uint32_t*>(&plo)) & mk.x;
                afr[mt][2 + hi] = (*reinterpret_cast<uint32_t*>(&phi)) & mk.y;
            }
            uint32_t rbase = sBu[buf] + (ks * 16 + row_l) * 128;
#pragma unroll
            for (int p = 0; p < 4; p++) {
                uint32_t b0, b1, b2, b3;
                asm volatile(
                    "ldmatrix.sync.aligned.m8n8.x4.trans.shared.b16 "
                    "{%0,%1,%2,%3}, [%4];"
                    : "=r"(b0), "=r"(b1), "=r"(b2), "=r"(b3)
                    : "r"(rbase + 16 * ((2 * p) ^ x_l)));
                mma16816(acc[0][2 * p], afr[0], b0, b1);
                mma16816(acc[0][2 * p + 1], afr[0], b2, b3);
                mma16816(acc[1][2 * p], afr[1], b0, b1);
                mma16816(acc[1][2 * p + 1], afr[1], b2, b3);
            }
            mma16816(accD[0], afr[0], bone, bone);
            mma16816(accD[1], afr[1], bone, bone);
        }
        __syncthreads();
    }

    if (tg == 0) {
#pragma unroll
        for (int mt = 0; mt < 2; mt++) {
            g_den[(size_t)(r * NSPL + split) * NV + rowg + 16 * mt] = accD[mt][0];
            g_den[(size_t)(r * NSPL + split) * NV + rowg + 16 * mt + 8] =
                accD[mt][2];
        }
    }
    __half* nb = g_num + (size_t)(r * NSPL + split) * NV * HD;
#pragma unroll
    for (int mt = 0; mt < 2; mt++)
#pragma unroll
        for (int ng = 0; ng < 8; ng++) {
            int col = ng * 8 + tg * 2;
            int R0 = rowg + 16 * mt;
            *(__half2*)&nb[(size_t)R0 * HD + col] =
                __floats2half2_rn(acc[mt][ng][0], acc[mt][ng][1]);
            *(__half2*)&nb[(size_t)(R0 + 8) * HD + col] =
                __floats2half2_rn(acc[mt][ng][2], acc[mt][ng][3]);
        }
}

// ---------------- 4. combine layer 2 + score head fused -------------------------
__global__ void combine_score_kernel(const float* __restrict__ bvec,
                                     const float* __restrict__ Wsv,
                                     const float* __restrict__ bs,
                                     float* __restrict__ out) {
    int tid = threadIdx.x;
    int gid = blockIdx.x * 256 + tid;
    int i = gid >> 5, c2 = (gid & 31) * 2;
    float2 v = make_float2(bvec[c2], bvec[c2 + 1]);
#pragma unroll
    for (int r = 0; r < RV; r++) {
        float2 num = make_float2(0.f, 0.f);
        float den = 0.f;
#pragma unroll
        for (int s = 0; s < NSPL; s++) {
            uint32_t nv =
                *(const uint32_t*)&g_num[(((size_t)(r * NSPL + s) * NV) + i) * HD + c2];
            float2 a = __half22float2(*(__half2*)&nv);
            num.x += a.x; num.y += a.y;
            den += g_den[(size_t)(r * NSPL + s) * NV + i];
        }
        if (den != 0.f) {
            float inv = __frcp_rn(den);
            v.x += num.x * inv; v.y += num.y * inv;
        }
    }
    float p = fmaxf(v.x, 0.f) * Wsv[c2] + fmaxf(v.y, 0.f) * Wsv[c2 + 1];
#pragma unroll
    for (int o = 16; o; o >>= 1) p += __shfl_down_sync(0xFFFFFFFFu, p, o);
    if ((tid & 31) == 0) out[i] = 1.f / (1.f + __expf(-(p + bs[0])));
}

// ---------------- launch --------------------------------------------------------
extern "C" void kernel_launch(void* const* d_in, const int* in_sizes, int n_in,
                              void* d_out, int out_size) {
    const float* Z  = (const float*)d_in[0];
    const int*   A0 = (const int*)d_in[1];
    const int*   A1 = (const int*)d_in[2];
    const int*   A2 = (const int*)d_in[3];
    const float* W1 = (const float*)d_in[4];
    const float* a1 = (const float*)d_in[5];
    const float* b1 = (const float*)d_in[6];
    const float* W2 = (const float*)d_in[7];
    const float* a2 = (const float*)d_in[8];
    const float* b2 = (const float*)d_in[9];
    const float* Ws = (const float*)d_in[10];
    const float* bs = (const float*)d_in[11];
    float* out = (float*)d_out;

    // layer 1 (pack co-scheduled with the gemm in one launch)
    fused_pack_gemm1<<<4288, 256>>>(Z, A0, A1, A2, W1, a1);
    attn_hmma_kernel<<<dim3(32, 3, NSPL), 128>>>();

    // layer 2 (combine fused into the gemm)
    combine_gemm2_kernel<<<dim3(64, 3), 256>>>(W2, a2, b1);
    attn_hmma_kernel<<<dim3(32, 3, NSPL), 128>>>();
    combine_score_kernel<<<512, 256>>>(b2, Ws, bs, out);
}

// round 13
// speedup vs baseline: 1.0343x; 1.0343x over previous
#include <cuda_runtime.h>
#include <cuda_fp16.h>
#include <cstdint>
#include <math.h>

#define NV 4096
#define HD 64
#define RV 3
#define WPR 128   // 32-bit words per adjacency row
#define NSPL 4    // j-splits of 1024

// ---------------- scratch ------------------------------------------------------
__device__ uint32_t g_bits[RV * NV * WPR];        // packed adjacency (6.3 MB)
__device__ float g_fi[RV * NV];
__device__ float g_fj[RV * NV];
__device__ __half g_Whh[RV * NV * HD];            // Wh in f16, [r][j][c]
__device__ float g_Hbuf[NV * HD];                 // H1
__device__ __half g_num[RV * NSPL * NV * HD];     // per (r, j-split) numerators (f16)
__device__ float g_den[RV * NSPL * NV];

__device__ __forceinline__ void cpa16(uint32_t d, const void* s) {
    asm volatile("cp.async.cg.shared.global [%0], [%1], 16;" :: "r"(d), "l"(s));
}
__device__ __forceinline__ void mma16816(float* d, const uint32_t* a,
                                         uint32_t b0, uint32_t b1) {
    asm volatile(
        "mma.sync.aligned.m16n8k16.row.col.f32.f16.f16.f32 "
        "{%0,%1,%2,%3}, {%4,%5,%6,%7}, {%8,%9}, {%0,%1,%2,%3};"
        : "+f"(d[0]), "+f"(d[1]), "+f"(d[2]), "+f"(d[3])
        : "r"(a[0]), "r"(a[1]), "r"(a[2]), "r"(a[3]), "r"(b0), "r"(b1));
}

// ---------------- shared gemm body ---------------------------------------------
template <int K>
__device__ __forceinline__ void gemm_body(float (*Hs)[64], float (*Wss)[64],
                                          const float* __restrict__ H, int r,
                                          int rowbase,
                                          const float* __restrict__ Wmat,
                                          const float* __restrict__ avec) {
    int tid = threadIdx.x;
    int tx = tid & 15, ty = tid >> 4;
    int i0 = ty * 4, c0 = tx * 4;
    float acc[4][4] = {};
    const float* Wr = Wmat + (size_t)r * K * HD;

    for (int kt = 0; kt < K; kt += 64) {
        {
            int i = tid >> 2, kk0 = (tid & 3) << 4;
            const float* src = H + (size_t)(rowbase + i) * K + kt + kk0;
#pragma unroll
            for (int q = 0; q < 4; q++) {
                float4 v = *(const float4*)(src + 4 * q);
                Hs[kk0 + 4 * q + 0][i] = v.x;
                Hs[kk0 + 4 * q + 1][i] = v.y;
                Hs[kk0 + 4 * q + 2][i] = v.z;
                Hs[kk0 + 4 * q + 3][i] = v.w;
            }
            const float4* wsrc = (const float4*)(Wr + (size_t)kt * HD);
            float4* wdst = (float4*)&Wss[0][0];
#pragma unroll
            for (int q = 0; q < 4; q++) wdst[tid + 256 * q] = wsrc[tid + 256 * q];
        }
        __syncthreads();
#pragma unroll 8
        for (int kk = 0; kk < 64; kk++) {
            float4 a = *(const float4*)&Hs[kk][i0];
            float4 b = *(const float4*)&Wss[kk][c0];
            float av[4] = {a.x, a.y, a.z, a.w};
            float bv[4] = {b.x, b.y, b.z, b.w};
#pragma unroll
            for (int ii = 0; ii < 4; ii++)
#pragma unroll
                for (int jj = 0; jj < 4; jj++)
                    acc[ii][jj] = fmaf(av[ii], bv[jj], acc[ii][jj]);
        }
        __syncthreads();
    }

#pragma unroll
    for (int ii = 0; ii < 4; ii++)
        *(float4*)&Hs[i0 + ii][c0] =
            make_float4(acc[ii][0], acc[ii][1], acc[ii][2], acc[ii][3]);
    __syncthreads();

    // f16 Wh store: [j][c]
    {
        int i = tid >> 2, cb = (tid & 3) * 16;
        uint32_t h2v[8];
#pragma unroll
        for (int q = 0; q < 8; q++) {
            __half2 h = __floats2half2_rn(Hs[i][cb + 2 * q], Hs[i][cb + 2 * q + 1]);
            h2v[q] = *reinterpret_cast<uint32_t*>(&h);
        }
        uint32_t* dst =
            (uint32_t*)(g_Whh + ((size_t)(r * NV + rowbase + i)) * HD + cb);
        *(uint4*)dst = make_uint4(h2v[0], h2v[1], h2v[2], h2v[3]);
        *(uint4*)(dst + 4) = make_uint4(h2v[4], h2v[5], h2v[6], h2v[7]);
    }

    int warp = tid >> 5, lane = tid & 31;
    const float* ar = avec + r * 2 * HD;
#pragma unroll
    for (int s = 0; s < 8; s++) {
        int i = warp * 8 + s;
        float h1 = Hs[i][lane], h2 = Hs[i][lane + 32];
        float pl = h1 * ar[lane] + h2 * ar[lane + 32];
        float pr = h1 * ar[HD + lane] + h2 * ar[HD + lane + 32];
#pragma unroll
        for (int o = 16; o; o >>= 1) {
            pl += __shfl_down_sync(0xFFFFFFFFu, pl, o);
            pr += __shfl_down_sync(0xFFFFFFFFu, pr, o);
        }
        if (lane == 0) {
            g_fi[r * NV + rowbase + i] = pl;
            g_fj[r * NV + rowbase + i] = pr;
        }
    }
}

// ---------------- 1. fused: pack (blocks >=192) + layer-1 gemm (blocks <192) ----
__global__ void __launch_bounds__(256) fused_pack_gemm1(
    const float* __restrict__ Z, const int* __restrict__ A0,
    const int* __restrict__ A1, const int* __restrict__ A2,
    const float* __restrict__ W1, const float* __restrict__ a1) {
    __shared__ float Hs[64][64];
    __shared__ float Wss[64][64];
    int bx = blockIdx.x;
    if (bx < 192) {
        gemm_body<128>(Hs, Wss, Z, bx >> 6, (bx & 63) * 64, W1, a1);
        return;
    }
    // pack path
    const int TOTQ = RV * NV * NV / 4;
    const int stride = 4096 * 256;
    int lane = threadIdx.x & 31;
    for (int t = (bx - 192) * 256 + threadIdx.x; t < TOTQ; t += stride) {
        int r = t >> 22;
        const int4* A = (const int4*)((r == 0) ? A0 : (r == 1) ? A1 : A2);
        int4 v = A[t & 0x3FFFFF];
        uint32_t nib = (v.x != 0 ? 1u : 0u) | (v.y != 0 ? 2u : 0u) |
                       (v.z != 0 ? 4u : 0u) | (v.w != 0 ? 8u : 0u);
        uint32_t m = nib << ((lane & 7) * 4);
        m |= __shfl_xor_sync(0xFFFFFFFFu, m, 1);
        m |= __shfl_xor_sync(0xFFFFFFFFu, m, 2);
        m |= __shfl_xor_sync(0xFFFFFFFFu, m, 4);
        if ((lane & 7) == 0) g_bits[t >> 3] = m;
    }
}

// ---------------- 2. layer-2 gemm ----------------------------------------------
__global__ void __launch_bounds__(256) gemm_wh2_kernel(
    const float* __restrict__ Wmat, const float* __restrict__ avec) {
    __shared__ float Hs[64][64];
    __shared__ float Wss[64][64];
    gemm_body<64>(Hs, Wss, g_Hbuf, blockIdx.y, blockIdx.x * 64, Wmat, avec);
}

// ---------------- 3. fused alpha-gen + HMMA aggregation -------------------------
// grid (32 i-tiles of 128 rows, 3 r, 4 j-splits of 1024); 128 threads / 4 warps.
// Single barrier per chunk: the top barrier of iter ch orders all reads of
// buffer (ch-1)%3 == (ch+2)%3 before stage() rewrites it (3-buffer rotation).
__global__ void __launch_bounds__(128, 4) attn_hmma_kernel() {
    int tid = threadIdx.x;
    int itile = blockIdx.x, r = blockIdx.y, split = blockIdx.z;
    int rowbase = itile * 128;
    int jw0 = split * 1024;

    __shared__ __align__(1024) uint8_t sB[3][8192];  // 64j x 64c f16, swizzled
    __shared__ uint32_t sBits[128 * 36];             // 128 rows, stride 36 words
    __shared__ uint4 sEF[256];                       // (group, tg) -> {E2lo,E2hi,F2lo,F2hi}
    __shared__ uint2 sLut[16];                       // nibble -> 2 half2 masks

    uint32_t sBu[3] = {(uint32_t)__cvta_generic_to_shared(&sB[0][0]),
                       (uint32_t)__cvta_generic_to_shared(&sB[1][0]),
                       (uint32_t)__cvta_generic_to_shared(&sB[2][0])};
    uint32_t sBitsu = (uint32_t)__cvta_generic_to_shared(sBits);

    if (tid < 16)
        sLut[tid] = make_uint2(
            ((tid & 1) ? 0xFFFFu : 0u) | ((tid & 2) ? 0xFFFF0000u : 0u),
            ((tid & 4) ? 0xFFFFu : 0u) | ((tid & 8) ? 0xFFFF0000u : 0u));

    // stage adjacency bits for this tile: 128 rows x 128B (once, coalesced)
#pragma unroll
    for (int q = 0; q < 8; q++) {
        int idx = tid + 128 * q;
        int row = idx >> 3, w16 = idx & 7;
        const uint32_t* src = g_bits + (size_t)(r * NV + rowbase + row) * WPR +
                              split * 32 + w16 * 4;
        cpa16(sBitsu + (row * 36 + w16 * 4) * 4, src);
    }

    // B chunk stager: rows placed at sigma(j) to match lane-contiguous j perm
    auto stage = [&](int ch, int buf) {
#pragma unroll
        for (int q = 0; q < 4; q++) {
            int g = tid + 128 * q;
            int j64 = g >> 3, c8 = g & 7;
            int j16 = j64 & 15, t = j16 >> 2, q2 = j16 & 3;
            int srow = (j64 & ~15) + 2 * t + (q2 & 1) + ((q2 >> 1) << 3);
            const __half* src =
                g_Whh + ((size_t)(r * NV + jw0 + ch * 64 + j64)) * HD + c8 * 8;
            cpa16(sBu[buf] + srow * 128 + 16 * (c8 ^ (srow & 7)), src);
        }
        asm volatile("cp.async.commit_group;" ::: "memory");
    };
    stage(0, 0);        // G0: bits + B0
    stage(1, 1);        // G1: B1

    // compute EF window (Ej = exp(fj), Fj = exp(0.2 fj)); entry e covers
    // j = jw0 + 4e + {0,1,2,3}, matching the sigma(j) B permutation.
    {
        const float* fjp = g_fj + r * NV + jw0;
#pragma unroll
        for (int q = 0; q < 2; q++) {
            int e = tid + 128 * q;
            float4 f = *(const float4*)&fjp[e * 4];
            __half2 e01 = __floats2half2_rn(__expf(f.x), __expf(f.y));
            __half2 e23 = __floats2half2_rn(__expf(f.z), __expf(f.w));
            __half2 f01 =
                __floats2half2_rn(__expf(0.2f * f.x), __expf(0.2f * f.y));
            __half2 f23 =
                __floats2half2_rn(__expf(0.2f * f.z), __expf(0.2f * f.w));
            sEF[e] = make_uint4(*reinterpret_cast<uint32_t*>(&e01),
                                *reinterpret_cast<uint32_t*>(&e23),
                                *reinterpret_cast<uint32_t*>(&f01),
                                *reinterpret_cast<uint32_t*>(&f23));
        }
    }

    int l = tid & 31, w = tid >> 5;
    int g4 = l >> 2, tg = l & 3;
    int rowloc = w * 32 + g4;                     // rows rowloc + 8*rr, rr<4
    int rowg = rowbase + rowloc;
    __half2 Ei2[4], Fi2[4];
#pragma unroll
    for (int rr = 0; rr < 4; rr++) {
        float u = g_fi[r * NV + rowg + 8 * rr];
        float ei = __expf(fminf(0.8f * u, 0.f));   // exp(u - lrelu(u))
        float fi_ = __expf(fminf(-0.8f * u, 0.f)); // exp(0.2u - lrelu(u))
        Ei2[rr] = __floats2half2_rn(ei, ei);
        Fi2[rr] = __floats2half2_rn(fi_, fi_);
    }

    int row_l = ((l >> 3) & 1) * 8 + (l & 7);     // ldmatrix row within k16
    int x_l = (l >> 4) ^ (row_l & 7);             // swizzle term

    float acc[2][8][4] = {};                      // [m-tile][n8][frag]
    float accD[2][4] = {};
    uint32_t bone = (l < 4) ? 0x3C003C00u : 0u;   // ones column (den)

    for (int ch = 0; ch < 16; ch++) {
        int buf = ch % 3;
        if (ch < 15)
            asm volatile("cp.async.wait_group 1;" ::: "memory");
        else
            asm volatile("cp.async.wait_group 0;" ::: "memory");
        __syncthreads();
        if (ch + 2 < 16) stage(ch + 2, (ch + 2) % 3);
        uint2 wbv[4];
#pragma unroll
        for (int rr = 0; rr < 4; rr++)
            wbv[rr] = *(const uint2*)&sBits[(rowloc + 8 * rr) * 36 + ch * 2];
#pragma unroll
        for (int ks = 0; ks < 4; ks++) {
            uint4 EF = sEF[ch * 16 + ks * 4 + tg];
            __half2 E2lo = *(__half2*)&EF.x, E2hi = *(__half2*)&EF.y;
            __half2 F2lo = *(__half2*)&EF.z, F2hi = *(__half2*)&EF.w;
            uint32_t afr[2][4];
#pragma unroll
            for (int rr = 0; rr < 4; rr++) {
                uint32_t wword = (ks < 2) ? wbv[rr].x : wbv[rr].y;
                uint32_t nib = (wword >> ((ks & 1) * 16 + tg * 4)) & 0xFu;
                uint2 mk = sLut[nib];
                __half2 plo =
                    __hmax2(__hmul2(Ei2[rr], E2lo), __hmul2(Fi2[rr], F2lo));
                __half2 phi =
                    __hmax2(__hmul2(Ei2[rr], E2hi), __hmul2(Fi2[rr], F2hi));
                int mt = rr >> 1, hi = rr & 1;
                afr[mt][hi] = (*reinterpret_cast<uint32_t*>(&plo)) & mk.x;
                afr[mt][2 + hi] = (*reinterpret_cast<uint32_t*>(&phi)) & mk.y;
            }
            uint32_t rbase = sBu[buf] + (ks * 16 + row_l) * 128;
#pragma unroll
            for (int p = 0; p < 4; p++) {
                uint32_t b0, b1, b2, b3;
                asm volatile(
                    "ldmatrix.sync.aligned.m8n8.x4.trans.shared.b16 "
                    "{%0,%1,%2,%3}, [%4];"
                    : "=r"(b0), "=r"(b1), "=r"(b2), "=r"(b3)
                    : "r"(rbase + 16 * ((2 * p) ^ x_l)));
                mma16816(acc[0][2 * p], afr[0], b0, b1);
                mma16816(acc[0][2 * p + 1], afr[0], b2, b3);
                mma16816(acc[1][2 * p], afr[1], b0, b1);
                mma16816(acc[1][2 * p + 1], afr[1], b2, b3);
            }
            mma16816(accD[0], afr[0], bone, bone);
            mma16816(accD[1], afr[1], bone, bone);
        }
        // no bottom barrier: next iteration's top barrier provides the ordering
    }

    if (tg == 0) {
#pragma unroll
        for (int mt = 0; mt < 2; mt++) {
            g_den[(size_t)(r * NSPL + split) * NV + rowg + 16 * mt] = accD[mt][0];
            g_den[(size_t)(r * NSPL + split) * NV + rowg + 16 * mt + 8] =
                accD[mt][2];
        }
    }
    __half* nb = g_num + (size_t)(r * NSPL + split) * NV * HD;
#pragma unroll
    for (int mt = 0; mt < 2; mt++)
#pragma unroll
        for (int ng = 0; ng < 8; ng++) {
            int col = ng * 8 + tg * 2;
            int R0 = rowg + 16 * mt;
            *(__half2*)&nb[(size_t)R0 * HD + col] =
                __floats2half2_rn(acc[mt][ng][0], acc[mt][ng][1]);
            *(__half2*)&nb[(size_t)(R0 + 8) * HD + col] =
                __floats2half2_rn(acc[mt][ng][2], acc[mt][ng][3]);
        }
}

// ---------------- 4a. combine layer 1: bias + relu -> H1 (half2/thread) ---------
__global__ void combine_kernel(const float* __restrict__ bvec) {
    int gid = blockIdx.x * 256 + threadIdx.x;     // grid 512 -> NV*HD/2 threads
    int i = gid >> 5, c2 = (gid & 31) * 2;
    float2 v = make_float2(bvec[c2], bvec[c2 + 1]);
#pragma unroll
    for (int r = 0; r < RV; r++) {
        float2 num = make_float2(0.f, 0.f);
        float den = 0.f;
#pragma unroll
        for (int s = 0; s < NSPL; s++) {
            uint32_t nv =
                *(const uint32_t*)&g_num[(((size_t)(r * NSPL + s) * NV) + i) * HD + c2];
            float2 a = __half22float2(*(__half2*)&nv);
            num.x += a.x; num.y += a.y;
            den += g_den[(size_t)(r * NSPL + s) * NV + i];
        }
        if (den != 0.f) {
            float inv = __frcp_rn(den);
            v.x += num.x * inv; v.y += num.y * inv;
        }
    }
    v.x = fmaxf(v.x, 0.f); v.y = fmaxf(v.y, 0.f);
    *(float2*)&g_Hbuf[(size_t)i * HD + c2] = v;
}

// ---------------- 4b. combine layer 2 + score head fused ------------------------
__global__ void combine_score_kernel(const float* __restrict__ bvec,
                                     const float* __restrict__ Wsv,
                                     const float* __restrict__ bs,
                                     float* __restrict__ out) {
    int tid = threadIdx.x;
    int gid = blockIdx.x * 256 + tid;
    int i = gid >> 5, c2 = (gid & 31) * 2;
    float2 v = make_float2(bvec[c2], bvec[c2 + 1]);
#pragma unroll
    for (int r = 0; r < RV; r++) {
        float2 num = make_float2(0.f, 0.f);
        float den = 0.f;
#pragma unroll
        for (int s = 0; s < NSPL; s++) {
            uint32_t nv =
                *(const uint32_t*)&g_num[(((size_t)(r * NSPL + s) * NV) + i) * HD + c2];
            float2 a = __half22float2(*(__half2*)&nv);
            num.x += a.x; num.y += a.y;
            den += g_den[(size_t)(r * NSPL + s) * NV + i];
        }
        if (den != 0.f) {
            float inv = __frcp_rn(den);
            v.x += num.x * inv; v.y += num.y * inv;
        }
    }
    float p = fmaxf(v.x, 0.f) * Wsv[c2] + fmaxf(v.y, 0.f) * Wsv[c2 + 1];
#pragma unroll
    for (int o = 16; o; o >>= 1) p += __shfl_down_sync(0xFFFFFFFFu, p, o);
    if ((tid & 31) == 0) out[i] = 1.f / (1.f + __expf(-(p + bs[0])));
}

// ---------------- launch --------------------------------------------------------
extern "C" void kernel_launch(void* const* d_in, const int* in_sizes, int n_in,
                              void* d_out, int out_size) {
    const float* Z  = (const float*)d_in[0];
    const int*   A0 = (const int*)d_in[1];
    const int*   A1 = (const int*)d_in[2];
    const int*   A2 = (const int*)d_in[3];
    const float* W1 = (const float*)d_in[4];
    const float* a1 = (const float*)d_in[5];
    const float* b1 = (const float*)d_in[6];
    const float* W2 = (const float*)d_in[7];
    const float* a2 = (const float*)d_in[8];
    const float* b2 = (const float*)d_in[9];
    const float* Ws = (const float*)d_in[10];
    const float* bs = (const float*)d_in[11];
    float* out = (float*)d_out;

    // layer 1 (pack co-scheduled with the gemm in one launch)
    fused_pack_gemm1<<<4288, 256>>>(Z, A0, A1, A2, W1, a1);
    attn_hmma_kernel<<<dim3(32, 3, NSPL), 128>>>();
    combine_kernel<<<512, 256>>>(b1);

    // layer 2
    gemm_wh2_kernel<<<dim3(64, 3), 256>>>(W2, a2);
    attn_hmma_kernel<<<dim3(32, 3, NSPL), 128>>>();
    combine_score_kernel<<<512, 256>>>(b2, Ws, bs, out);
}

// round 14
// speedup vs baseline: 1.0667x; 1.0313x over previous
#include <cuda_runtime.h>
#include <cuda_fp16.h>
#include <cstdint>
#include <math.h>

#define NV 4096
#define HD 64
#define RV 3
#define WPR 128   // 32-bit words per adjacency row
#define NSPL 4    // j-splits of 1024

// ---------------- scratch ------------------------------------------------------
__device__ uint32_t g_bits[RV * NV * WPR];        // packed adjacency (6.3 MB)
__device__ float g_fi[RV * NV];
__device__ float g_fj[RV * NV];
__device__ __half g_Whh[RV * NV * HD];            // Wh in f16, [r][j][c]
__device__ __half g_num[RV * NSPL * NV * HD];     // per (r, j-split) numerators (f16)
__device__ float g_den[RV * NSPL * NV];

__device__ __forceinline__ void cpa16(uint32_t d, const void* s) {
    asm volatile("cp.async.cg.shared.global [%0], [%1], 16;" :: "r"(d), "l"(s));
}
__device__ __forceinline__ void mma16816(float* d, const uint32_t* a,
                                         uint32_t b0, uint32_t b1) {
    asm volatile(
        "mma.sync.aligned.m16n8k16.row.col.f32.f16.f16.f32 "
        "{%0,%1,%2,%3}, {%4,%5,%6,%7}, {%8,%9}, {%0,%1,%2,%3};"
        : "+f"(d[0]), "+f"(d[1]), "+f"(d[2]), "+f"(d[3])
        : "r"(a[0]), "r"(a[1]), "r"(a[2]), "r"(a[3]), "r"(b0), "r"(b1));
}

// ---------------- shared gemm epilogue (Hs holds output tile [i][c]) ------------
__device__ __forceinline__ void wh_epilogue(float (*Hs)[64], int r, int rowbase,
                                            const float* __restrict__ avec) {
    int tid = threadIdx.x;
    // f16 Wh store: [j][c]
    {
        int i = tid >> 2, cb = (tid & 3) * 16;
        uint32_t h2v[8];
#pragma unroll
        for (int q = 0; q < 8; q++) {
            __half2 h = __floats2half2_rn(Hs[i][cb + 2 * q], Hs[i][cb + 2 * q + 1]);
            h2v[q] = *reinterpret_cast<uint32_t*>(&h);
        }
        uint32_t* dst =
            (uint32_t*)(g_Whh + ((size_t)(r * NV + rowbase + i)) * HD + cb);
        *(uint4*)dst = make_uint4(h2v[0], h2v[1], h2v[2], h2v[3]);
        *(uint4*)(dst + 4) = make_uint4(h2v[4], h2v[5], h2v[6], h2v[7]);
    }
    int warp = tid >> 5, lane = tid & 31;
    const float* ar = avec + r * 2 * HD;
#pragma unroll
    for (int s = 0; s < 8; s++) {
        int i = warp * 8 + s;
        float h1 = Hs[i][lane], h2 = Hs[i][lane + 32];
        float pl = h1 * ar[lane] + h2 * ar[lane + 32];
        float pr = h1 * ar[HD + lane] + h2 * ar[HD + lane + 32];
#pragma unroll
        for (int o = 16; o; o >>= 1) {
            pl += __shfl_down_sync(0xFFFFFFFFu, pl, o);
            pr += __shfl_down_sync(0xFFFFFFFFu, pr, o);
        }
        if (lane == 0) {
            g_fi[r * NV + rowbase + i] = pl;
            g_fj[r * NV + rowbase + i] = pr;
        }
    }
}

// ---------------- 1. fused: pack (blocks >=192) + layer-1 gemm (blocks <192) ----
__global__ void __launch_bounds__(256) fused_pack_gemm1(
    const float* __restrict__ Z, const int* __restrict__ A0,
    const int* __restrict__ A1, const int* __restrict__ A2,
    const float* __restrict__ W1, const float* __restrict__ a1) {
    __shared__ float Hs[64][64];
    __shared__ float Wss[64][64];
    int bx = blockIdx.x;
    int tid = threadIdx.x;
    if (bx < 192) {
        int r = bx >> 6, rowbase = (bx & 63) * 64;
        const float* Wr = W1 + (size_t)r * 128 * HD;
        int tx = tid & 15, ty = tid >> 4;
        int i0 = ty * 4, c0 = tx * 4;
        float acc[4][4] = {};
        for (int kt = 0; kt < 128; kt += 64) {
            {
                int i = tid >> 2, kk0 = (tid & 3) << 4;
                const float* src = Z + (size_t)(rowbase + i) * 128 + kt + kk0;
#pragma unroll
                for (int q = 0; q < 4; q++) {
                    float4 v = *(const float4*)(src + 4 * q);
                    Hs[kk0 + 4 * q + 0][i] = v.x;
                    Hs[kk0 + 4 * q + 1][i] = v.y;
                    Hs[kk0 + 4 * q + 2][i] = v.z;
                    Hs[kk0 + 4 * q + 3][i] = v.w;
                }
                const float4* wsrc = (const float4*)(Wr + (size_t)kt * HD);
                float4* wdst = (float4*)&Wss[0][0];
#pragma unroll
                for (int q = 0; q < 4; q++)
                    wdst[tid + 256 * q] = wsrc[tid + 256 * q];
            }
            __syncthreads();
#pragma unroll 8
            for (int kk = 0; kk < 64; kk++) {
                float4 a = *(const float4*)&Hs[kk][i0];
                float4 b = *(const float4*)&Wss[kk][c0];
                float av[4] = {a.x, a.y, a.z, a.w};
                float bv[4] = {b.x, b.y, b.z, b.w};
#pragma unroll
                for (int ii = 0; ii < 4; ii++)
#pragma unroll
                    for (int jj = 0; jj < 4; jj++)
                        acc[ii][jj] = fmaf(av[ii], bv[jj], acc[ii][jj]);
            }
            __syncthreads();
        }
#pragma unroll
        for (int ii = 0; ii < 4; ii++)
            *(float4*)&Hs[i0 + ii][c0] =
                make_float4(acc[ii][0], acc[ii][1], acc[ii][2], acc[ii][3]);
        __syncthreads();
        wh_epilogue(Hs, r, rowbase, a1);
        return;
    }
    // pack path
    const int TOTQ = RV * NV * NV / 4;
    const int stride = 4096 * 256;
    int lane = threadIdx.x & 31;
    for (int t = (bx - 192) * 256 + threadIdx.x; t < TOTQ; t += stride) {
        int r = t >> 22;
        const int4* A = (const int4*)((r == 0) ? A0 : (r == 1) ? A1 : A2);
        int4 v = A[t & 0x3FFFFF];
        uint32_t nib = (v.x != 0 ? 1u : 0u) | (v.y != 0 ? 2u : 0u) |
                       (v.z != 0 ? 4u : 0u) | (v.w != 0 ? 8u : 0u);
        uint32_t m = nib << ((lane & 7) * 4);
        m |= __shfl_xor_sync(0xFFFFFFFFu, m, 1);
        m |= __shfl_xor_sync(0xFFFFFFFFu, m, 2);
        m |= __shfl_xor_sync(0xFFFFFFFFu, m, 4);
        if ((lane & 7) == 0) g_bits[t >> 3] = m;
    }
}

// ---------------- 2. fused combine(layer1) + layer-2 gemm -----------------------
// grid (64, 3). Combine phase uses the coalesced warp-per-row pattern; H1 tile
// stored row-major [i][k] in smem (conflict-free), gemm reads k-column with
// 2-way broadcast scalar LDS.
__global__ void __launch_bounds__(256) combine_gemm2_kernel(
    const float* __restrict__ Wmat, const float* __restrict__ avec,
    const float* __restrict__ bvec) {
    __shared__ float Hs[64][64];                  // [i][k] then reused [i][c]
    __shared__ float Wss[64][64];                 // [k][c]
    __shared__ float sDinv[RV * 64];
    int tid = threadIdx.x;
    int r = blockIdx.y;
    int rowbase = blockIdx.x * 64;

    // W load (long-latency; overlaps combine)
    {
        const float4* wsrc = (const float4*)(Wmat + (size_t)r * 64 * HD);
        float4* wdst = (float4*)&Wss[0][0];
#pragma unroll
        for (int q = 0; q < 4; q++) wdst[tid + 256 * q] = wsrc[tid + 256 * q];
    }

    // per-row 1/den (dinv==0 encodes isolated rows)
    if (tid < 64) {
        int i = rowbase + tid;
#pragma unroll
        for (int r2 = 0; r2 < RV; r2++) {
            float d = 0.f;
#pragma unroll
            for (int s = 0; s < NSPL; s++)
                d += g_den[(size_t)(r2 * NSPL + s) * NV + i];
            sDinv[r2 * 64 + tid] = (d != 0.f) ? __frcp_rn(d) : 0.f;
        }
    }
    __syncthreads();

    // combine: warp-per-row, 64 consecutive cols per warp (coalesced)
#pragma unroll
    for (int it = 0; it < 8; it++) {
        int g = it * 256 + tid;
        int row = g >> 5, c2 = (g & 31) * 2;
        int i = rowbase + row;
        float2 v = make_float2(bvec[c2], bvec[c2 + 1]);
#pragma unroll
        for (int r2 = 0; r2 < RV; r2++) {
            float2 num = make_float2(0.f, 0.f);
#pragma unroll
            for (int s = 0; s < NSPL; s++) {
                uint32_t nv = *(const uint32_t*)&g_num[
                    (((size_t)(r2 * NSPL + s) * NV) + i) * HD + c2];
                float2 a = __half22float2(*(__half2*)&nv);
                num.x += a.x; num.y += a.y;
            }
            float dinv = sDinv[r2 * 64 + row];
            v.x += num.x * dinv;
            v.y += num.y * dinv;
        }
        Hs[row][c2] = fmaxf(v.x, 0.f);
        Hs[row][c2 + 1] = fmaxf(v.y, 0.f);
    }
    __syncthreads();

    // gemm: acc[ii][jj] += H1[i0+ii][kk] * W[kk][c0+jj]
    int tx = tid & 15, ty = tid >> 4;
    int i0 = ty * 4, c0 = tx * 4;
    float acc[4][4] = {};
#pragma unroll 8
    for (int kk = 0; kk < 64; kk++) {
        float av[4] = {Hs[i0][kk], Hs[i0 + 1][kk], Hs[i0 + 2][kk],
                       Hs[i0 + 3][kk]};
        float4 b = *(const float4*)&Wss[kk][c0];
        float bv[4] = {b.x, b.y, b.z, b.w};
#pragma unroll
        for (int ii = 0; ii < 4; ii++)
#pragma unroll
            for (int jj = 0; jj < 4; jj++)
                acc[ii][jj] = fmaf(av[ii], bv[jj], acc[ii][jj]);
    }
    __syncthreads();

#pragma unroll
    for (int ii = 0; ii < 4; ii++)
        *(float4*)&Hs[i0 + ii][c0] =
            make_float4(acc[ii][0], acc[ii][1], acc[ii][2], acc[ii][3]);
    __syncthreads();

    wh_epilogue(Hs, r, rowbase, avec);
}

// ---------------- 3. fused alpha-gen + HMMA aggregation -------------------------
// grid (32 i-tiles of 128 rows, 3 r, 4 j-splits of 1024); 128 threads / 4 warps.
__global__ void __launch_bounds__(128, 4) attn_hmma_kernel() {
    int tid = threadIdx.x;
    int itile = blockIdx.x, r = blockIdx.y, split = blockIdx.z;
    int rowbase = itile * 128;
    int jw0 = split * 1024;

    __shared__ __align__(1024) uint8_t sB[3][8192];  // 64j x 64c f16, swizzled
    __shared__ uint32_t sBits[128 * 36];             // 128 rows, stride 36 words
    __shared__ uint4 sEF[256];                       // (group, tg) -> {E2lo,E2hi,F2lo,F2hi}
    __shared__ uint2 sLut[16];                       // nibble -> 2 half2 masks

    uint32_t sBu[3] = {(uint32_t)__cvta_generic_to_shared(&sB[0][0]),
                       (uint32_t)__cvta_generic_to_shared(&sB[1][0]),
                       (uint32_t)__cvta_generic_to_shared(&sB[2][0])};
    uint32_t sBitsu = (uint32_t)__cvta_generic_to_shared(sBits);

    if (tid < 16)
        sLut[tid] = make_uint2(
            ((tid & 1) ? 0xFFFFu : 0u) | ((tid & 2) ? 0xFFFF0000u : 0u),
            ((tid & 4) ? 0xFFFFu : 0u) | ((tid & 8) ? 0xFFFF0000u : 0u));

    // stage adjacency bits for this tile: 128 rows x 128B (once, coalesced)
#pragma unroll
    for (int q = 0; q < 8; q++) {
        int idx = tid + 128 * q;
        int row = idx >> 3, w16 = idx & 7;
        const uint32_t* src = g_bits + (size_t)(r * NV + rowbase + row) * WPR +
                              split * 32 + w16 * 4;
        cpa16(sBitsu + (row * 36 + w16 * 4) * 4, src);
    }

    // B chunk stager: rows placed at sigma(j) to match lane-contiguous j perm
    auto stage = [&](int ch, int buf) {
#pragma unroll
        for (int q = 0; q < 4; q++) {
            int g = tid + 128 * q;
            int j64 = g >> 3, c8 = g & 7;
            int j16 = j64 & 15, t = j16 >> 2, q2 = j16 & 3;
            int srow = (j64 & ~15) + 2 * t + (q2 & 1) + ((q2 >> 1) << 3);
            const __half* src =
                g_Whh + ((size_t)(r * NV + jw0 + ch * 64 + j64)) * HD + c8 * 8;
            cpa16(sBu[buf] + srow * 128 + 16 * (c8 ^ (srow & 7)), src);
        }
        asm volatile("cp.async.commit_group;" ::: "memory");
    };
    stage(0, 0);        // G0: bits + B0
    stage(1, 1);        // G1: B1

    // compute EF window (Ej = exp(fj), Fj = exp(0.2 fj)); entry e covers
    // j = jw0 + 4e + {0,1,2,3}, matching the sigma(j) B permutation.
    {
        const float* fjp = g_fj + r * NV + jw0;
#pragma unroll
        for (int q = 0; q < 2; q++) {
            int e = tid + 128 * q;
            float4 f = *(const float4*)&fjp[e * 4];
            __half2 e01 = __floats2half2_rn(__expf(f.x), __expf(f.y));
            __half2 e23 = __floats2half2_rn(__expf(f.z), __expf(f.w));
            __half2 f01 =
                __floats2half2_rn(__expf(0.2f * f.x), __expf(0.2f * f.y));
            __half2 f23 =
                __floats2half2_rn(__expf(0.2f * f.z), __expf(0.2f * f.w));
            sEF[e] = make_uint4(*reinterpret_cast<uint32_t*>(&e01),
                                *reinterpret_cast<uint32_t*>(&e23),
                                *reinterpret_cast<uint32_t*>(&f01),
                                *reinterpret_cast<uint32_t*>(&f23));
        }
    }

    int l = tid & 31, w = tid >> 5;
    int g4 = l >> 2, tg = l & 3;
    int rowloc = w * 32 + g4;                     // rows rowloc + 8*rr, rr<4
    int rowg = rowbase + rowloc;
    __half2 Ei2[4], Fi2[4];
#pragma unroll
    for (int rr = 0; rr < 4; rr++) {
        float u = g_fi[r * NV + rowg + 8 * rr];
        float ei = __expf(fminf(0.8f * u, 0.f));   // exp(u - lrelu(u))
        float fi_ = __expf(fminf(-0.8f * u, 0.f)); // exp(0.2u - lrelu(u))
        Ei2[rr] = __floats2half2_rn(ei, ei);
        Fi2[rr] = __floats2half2_rn(fi_, fi_);
    }

    int row_l = ((l >> 3) & 1) * 8 + (l & 7);     // ldmatrix row within k16
    int x_l = (l >> 4) ^ (row_l & 7);             // swizzle term

    float acc[2][8][4] = {};                      // [m-tile][n8][frag]
    float accD[2][4] = {};
    uint32_t bone = (l < 4) ? 0x3C003C00u : 0u;   // ones column (den)

    for (int ch = 0; ch < 16; ch++) {
        int buf = ch % 3;
        if (ch < 15)
            asm volatile("cp.async.wait_group 1;" ::: "memory");
        else
            asm volatile("cp.async.wait_group 0;" ::: "memory");
        __syncthreads();
        if (ch + 2 < 16) stage(ch + 2, (ch + 2) % 3);
        uint2 wbv[4];
#pragma unroll
        for (int rr = 0; rr < 4; rr++)
            wbv[rr] = *(const uint2*)&sBits[(rowloc + 8 * rr) * 36 + ch * 2];
#pragma unroll
        for (int ks = 0; ks < 4; ks++) {
            uint4 EF = sEF[ch * 16 + ks * 4 + tg];
            __half2 E2lo = *(__half2*)&EF.x, E2hi = *(__half2*)&EF.y;
            __half2 F2lo = *(__half2*)&EF.z, F2hi = *(__half2*)&EF.w;
            uint32_t afr[2][4];
#pragma unroll
            for (int rr = 0; rr < 4; rr++) {
                uint32_t wword = (ks < 2) ? wbv[rr].x : wbv[rr].y;
                uint32_t nib = (wword >> ((ks & 1) * 16 + tg * 4)) & 0xFu;
                uint2 mk = sLut[nib];
                __half2 plo =
                    __hmax2(__hmul2(Ei2[rr], E2lo), __hmul2(Fi2[rr], F2lo));
                __half2 phi =
                    __hmax2(__hmul2(Ei2[rr], E2hi), __hmul2(Fi2[rr], F2hi));
                int mt = rr >> 1, hi = rr & 1;
                afr[mt][hi] = (*reinterpret_cast<uint32_t*>(&plo)) & mk.x;
                afr[mt][2 + hi] = (*reinterpret_cast<uint32_t*>(&phi)) & mk.y;
            }
            uint32_t rbase = sBu[buf] + (ks * 16 + row_l) * 128;
#pragma unroll
            for (int p = 0; p < 4; p++) {
                uint32_t b0, b1, b2, b3;
                asm volatile(
                    "ldmatrix.sync.aligned.m8n8.x4.trans.shared.b16 "
                    "{%0,%1,%2,%3}, [%4];"
                    : "=r"(b0), "=r"(b1), "=r"(b2), "=r"(b3)
                    : "r"(rbase + 16 * ((2 * p) ^ x_l)));
                mma16816(acc[0][2 * p], afr[0], b0, b1);
                mma16816(acc[0][2 * p + 1], afr[0], b2, b3);
                mma16816(acc[1][2 * p], afr[1], b0, b1);
                mma16816(acc[1][2 * p + 1], afr[1], b2, b3);
            }
            mma16816(accD[0], afr[0], bone, bone);
            mma16816(accD[1], afr[1], bone, bone);
        }
        __syncthreads();
    }

    if (tg == 0) {
#pragma unroll
        for (int mt = 0; mt < 2; mt++) {
            g_den[(size_t)(r * NSPL + split) * NV + rowg + 16 * mt] = accD[mt][0];
            g_den[(size_t)(r * NSPL + split) * NV + rowg + 16 * mt + 8] =
                accD[mt][2];
        }
    }
    __half* nb = g_num + (size_t)(r * NSPL + split) * NV * HD;
#pragma unroll
    for (int mt = 0; mt < 2; mt++)
#pragma unroll
        for (int ng = 0; ng < 8; ng++) {
            int col = ng * 8 + tg * 2;
            int R0 = rowg + 16 * mt;
            *(__half2*)&nb[(size_t)R0 * HD + col] =
                __floats2half2_rn(acc[mt][ng][0], acc[mt][ng][1]);
            *(__half2*)&nb[(size_t)(R0 + 8) * HD + col] =
                __floats2half2_rn(acc[mt][ng][2], acc[mt][ng][3]);
        }
}

// ---------------- 4. combine layer 2 + score head fused -------------------------
__global__ void combine_score_kernel(const float* __restrict__ bvec,
                                     const float* __restrict__ Wsv,
                                     const float* __restrict__ bs,
                                     float* __restrict__ out) {
    int tid = threadIdx.x;
    int gid = blockIdx.x * 256 + tid;
    int i = gid >> 5, c2 = (gid & 31) * 2;
    float2 v = make_float2(bvec[c2], bvec[c2 + 1]);
#pragma unroll
    for (int r = 0; r < RV; r++) {
        float2 num = make_float2(0.f, 0.f);
        float den = 0.f;
#pragma unroll
        for (int s = 0; s < NSPL; s++) {
            uint32_t nv =
                *(const uint32_t*)&g_num[(((size_t)(r * NSPL + s) * NV) + i) * HD + c2];
            float2 a = __half22float2(*(__half2*)&nv);
            num.x += a.x; num.y += a.y;
            den += g_den[(size_t)(r * NSPL + s) * NV + i];
        }
        if (den != 0.f) {
            float inv = __frcp_rn(den);
            v.x += num.x * inv; v.y += num.y * inv;
        }
    }
    float p = fmaxf(v.x, 0.f) * Wsv[c2] + fmaxf(v.y, 0.f) * Wsv[c2 + 1];
#pragma unroll
    for (int o = 16; o; o >>= 1) p += __shfl_down_sync(0xFFFFFFFFu, p, o);
    if ((tid & 31) == 0) out[i] = 1.f / (1.f + __expf(-(p + bs[0])));
}

// ---------------- launch --------------------------------------------------------
extern "C" void kernel_launch(void* const* d_in, const int* in_sizes, int n_in,
                              void* d_out, int out_size) {
    const float* Z  = (const float*)d_in[0];
    const int*   A0 = (const int*)d_in[1];
    const int*   A1 = (const int*)d_in[2];
    const int*   A2 = (const int*)d_in[3];
    const float* W1 = (const float*)d_in[4];
    const float* a1 = (const float*)d_in[5];
    const float* b1 = (const float*)d_in[6];
    const float* W2 = (const float*)d_in[7];
    const float* a2 = (const float*)d_in[8];
    const float* b2 = (const float*)d_in[9];
    const float* Ws = (const float*)d_in[10];
    const float* bs = (const float*)d_in[11];
    float* out = (float*)d_out;

    // layer 1 (pack co-scheduled with the gemm in one launch)
    fused_pack_gemm1<<<4288, 256>>>(Z, A0, A1, A2, W1, a1);
    attn_hmma_kernel<<<dim3(32, 3, NSPL), 128>>>();

    // layer 2 (combine fused into the gemm, coalesced combine phase)
    combine_gemm2_kernel<<<dim3(64, 3), 256>>>(W2, a2, b1);
    attn_hmma_kernel<<<dim3(32, 3, NSPL), 128>>>();
    combine_score_kernel<<<512, 256>>>(b2, Ws, bs, out);
}